// round 1
// baseline (speedup 1.0000x reference)
#include <cuda_runtime.h>
#include <cstdint>

#define SS 4
#define NN 4096
#define DD 64

// Scratch for Q[s,j,d] = sum_e x0[s,j,e] * W[d,e]  (4 MB, static — no allocs allowed)
__device__ float g_Q[(size_t)SS * NN * DD];

// ---------------------------------------------------------------------------
// Stage 1: Q = x0 @ W^T   (tiny: 67 MFMA)
// One thread per row j; W cached in smem; float4 throughout.
// ---------------------------------------------------------------------------
__global__ __launch_bounds__(256) void q_kernel(const float* __restrict__ x0,
                                                const float* __restrict__ W) {
    __shared__ float Ws[DD * DD];
    int tid = threadIdx.x;
    // load W (64x64 = 4096 floats = 1024 float4) into smem
    #pragma unroll
    for (int i = tid; i < DD * DD / 4; i += 256)
        ((float4*)Ws)[i] = ((const float4*)W)[i];
    __syncthreads();

    int row = blockIdx.x * 256 + tid;          // 0 .. S*N-1
    const float4* xr = (const float4*)(x0 + (size_t)row * DD);
    float4 x[16];
    #pragma unroll
    for (int e = 0; e < 16; ++e) x[e] = xr[e];

    float4* q = (float4*)(g_Q + (size_t)row * DD);
    #pragma unroll
    for (int d4 = 0; d4 < 16; ++d4) {
        float r[4];
        #pragma unroll
        for (int dd = 0; dd < 4; ++dd) {
            int d = d4 * 4 + dd;
            const float4* wr = (const float4*)(Ws + d * DD);
            float a0 = 0.f, a1 = 0.f, a2 = 0.f, a3 = 0.f;
            #pragma unroll
            for (int e4 = 0; e4 < 16; e4 += 4) {
                float4 w0 = wr[e4 + 0], w1 = wr[e4 + 1], w2 = wr[e4 + 2], w3 = wr[e4 + 3];
                a0 += x[e4 + 0].x * w0.x + x[e4 + 0].y * w0.y + x[e4 + 0].z * w0.z + x[e4 + 0].w * w0.w;
                a1 += x[e4 + 1].x * w1.x + x[e4 + 1].y * w1.y + x[e4 + 1].z * w1.z + x[e4 + 1].w * w1.w;
                a2 += x[e4 + 2].x * w2.x + x[e4 + 2].y * w2.y + x[e4 + 2].z * w2.z + x[e4 + 2].w * w2.w;
                a3 += x[e4 + 3].x * w3.x + x[e4 + 3].y * w3.y + x[e4 + 3].z * w3.z + x[e4 + 3].w * w3.w;
            }
            r[dd] = (a0 + a1) + (a2 + a3);
        }
        q[d4] = make_float4(r[0], r[1], r[2], r[3]);
    }
}

// ---------------------------------------------------------------------------
// Packed fp32x2 helpers (Blackwell double-rate fp32 — ptxas never emits these
// from plain C++; must hand-write PTX).
// ---------------------------------------------------------------------------
__device__ __forceinline__ unsigned long long pk2(float lo, float hi) {
    unsigned long long r;
    asm("mov.b64 %0, {%1, %2};" : "=l"(r) : "f"(lo), "f"(hi));
    return r;
}
__device__ __forceinline__ void fma2(unsigned long long& d, unsigned long long a,
                                     unsigned long long b) {
    asm("fma.rn.f32x2 %0, %1, %2, %0;" : "+l"(d) : "l"(a), "l"(b));
}
__device__ __forceinline__ float2 upk2(unsigned long long v) {
    float2 r;
    asm("mov.b64 {%0, %1}, %2;" : "=f"(r.x), "=f"(r.y) : "l"(v));
    return r;
}

// ---------------------------------------------------------------------------
// Stage 2: out[s,i,j] = sum_d x1[s,i,d] * Q[s,j,d]  (NT GEMM, K=64 resident)
// 128x128 block tile, 256 threads, 8x8 per thread, f32x2 accumulators.
// Epilogue writes BOTH batch copies (out is tiled to batch 2).
// ---------------------------------------------------------------------------
__global__ __launch_bounds__(256, 2) void gemm_nt_kernel(const float* __restrict__ x1,
                                                         const float* __restrict__ bias,
                                                         float* __restrict__ out) {
    extern __shared__ float smem[];
    float* As = smem;              // [64][128] k-major: As[k*128 + i]
    float* Bs = smem + 64 * 128;   // [64][128] k-major: Bs[k*128 + j]

    const int tid = threadIdx.x;
    const int s = blockIdx.z;
    const int bi = blockIdx.y;     // i tile
    const int bj = blockIdx.x;     // j tile

    const float4* Ag = (const float4*)(x1 + ((size_t)s * NN + (size_t)bi * 128) * DD);
    const float4* Bg = (const float4*)(g_Q + ((size_t)s * NN + (size_t)bj * 128) * DD);

    // Load both 128x64 tiles, transposing to k-major.
    // Mapping: lanes take consecutive rows -> conflict-free smem stores.
    #pragma unroll
    for (int it = 0; it < 8; ++it) {
        int idx = it * 256 + tid;          // float4 index, 0..2047
        int row = idx & 127;
        int c4  = idx >> 7;                // 0..15
        int k0  = c4 * 4;
        float4 va = Ag[row * 16 + c4];
        float4 vb = Bg[row * 16 + c4];
        As[(k0 + 0) * 128 + row] = va.x;
        As[(k0 + 1) * 128 + row] = va.y;
        As[(k0 + 2) * 128 + row] = va.z;
        As[(k0 + 3) * 128 + row] = va.w;
        Bs[(k0 + 0) * 128 + row] = vb.x;
        Bs[(k0 + 1) * 128 + row] = vb.y;
        Bs[(k0 + 2) * 128 + row] = vb.z;
        Bs[(k0 + 3) * 128 + row] = vb.w;
    }
    __syncthreads();

    const int tx = tid & 15;   // j micro-tile
    const int ty = tid >> 4;   // i micro-tile

    unsigned long long acc[8][4];
    #pragma unroll
    for (int i = 0; i < 8; ++i)
        #pragma unroll
        for (int jp = 0; jp < 4; ++jp) acc[i][jp] = 0ull;  // two packed 0.0f

    const float* ap = As + ty * 8;
    const float* bp = Bs + tx * 8;

    #pragma unroll 8
    for (int k = 0; k < 64; ++k) {
        float4 a0 = *(const float4*)(ap + k * 128);
        float4 a1 = *(const float4*)(ap + k * 128 + 4);
        float4 b0 = *(const float4*)(bp + k * 128);
        float4 b1 = *(const float4*)(bp + k * 128 + 4);
        unsigned long long b2[4] = {pk2(b0.x, b0.y), pk2(b0.z, b0.w),
                                    pk2(b1.x, b1.y), pk2(b1.z, b1.w)};
        float av[8] = {a0.x, a0.y, a0.z, a0.w, a1.x, a1.y, a1.z, a1.w};
        #pragma unroll
        for (int i = 0; i < 8; ++i) {
            unsigned long long ai = pk2(av[i], av[i]);
            #pragma unroll
            for (int jp = 0; jp < 4; ++jp) fma2(acc[i][jp], ai, b2[jp]);
        }
    }

    const float bv = *bias;

    const size_t i0 = (size_t)bi * 128 + (size_t)ty * 8;
    const size_t j0 = (size_t)bj * 128 + (size_t)tx * 8;
    float* o0 = out + ((size_t)s * NN + i0) * NN + j0;       // batch 0
    const size_t BSTRIDE = (size_t)SS * NN * NN;             // batch 1 offset

    #pragma unroll
    for (int i = 0; i < 8; ++i) {
        float2 p0 = upk2(acc[i][0]);
        float2 p1 = upk2(acc[i][1]);
        float2 p2 = upk2(acc[i][2]);
        float2 p3 = upk2(acc[i][3]);
        float4 v0 = make_float4(p0.x + bv, p0.y + bv, p1.x + bv, p1.y + bv);
        float4 v1 = make_float4(p2.x + bv, p2.y + bv, p3.x + bv, p3.y + bv);
        float4* dst0 = (float4*)(o0 + (size_t)i * NN);
        dst0[0] = v0;
        dst0[1] = v1;
        float4* dst1 = (float4*)(o0 + BSTRIDE + (size_t)i * NN);
        dst1[0] = v0;
        dst1[1] = v1;
    }
}

// ---------------------------------------------------------------------------
// Launch
// ---------------------------------------------------------------------------
extern "C" void kernel_launch(void* const* d_in, const int* in_sizes, int n_in,
                              void* d_out, int out_size) {
    const float* x0   = (const float*)d_in[0];  // tensor0 (S,N,D)
    const float* x1   = (const float*)d_in[1];  // tensor1 (S,N,D)
    const float* W    = (const float*)d_in[2];  // kernel (D,D)
    const float* bias = (const float*)d_in[3];  // scalar
    float* out = (float*)d_out;                 // (2,S,N,N)

    q_kernel<<<(SS * NN) / 256, 256>>>(x0, W);

    cudaFuncSetAttribute(gemm_nt_kernel, cudaFuncAttributeMaxDynamicSharedMemorySize,
                         64 * 1024);
    dim3 grid(NN / 128, NN / 128, SS);
    gemm_nt_kernel<<<grid, 256, 64 * 1024>>>(x1, bias, out);
}

// round 3
// speedup vs baseline: 1.7812x; 1.7812x over previous
#include <cuda_runtime.h>
#include <cuda_bf16.h>
#include <cstdint>

#define SS 4
#define NN 4096
#define DD 64

// Scratch for Q[s,j,d] = sum_e x0[s,j,e] * W[d,e]  (4 MB, static — no allocs allowed)
__device__ float g_Q[(size_t)SS * NN * DD];

// ---------------------------------------------------------------------------
// Stage 1: Q = x0 @ W^T   (tiny: 67 MFMA)
// ---------------------------------------------------------------------------
__global__ __launch_bounds__(256) void q_kernel(const float* __restrict__ x0,
                                                const float* __restrict__ W) {
    __shared__ float Ws[DD * DD];
    int tid = threadIdx.x;
    #pragma unroll
    for (int i = tid; i < DD * DD / 4; i += 256)
        ((float4*)Ws)[i] = ((const float4*)W)[i];
    __syncthreads();

    int row = blockIdx.x * 256 + tid;
    const float4* xr = (const float4*)(x0 + (size_t)row * DD);
    float4 x[16];
    #pragma unroll
    for (int e = 0; e < 16; ++e) x[e] = xr[e];

    float4* q = (float4*)(g_Q + (size_t)row * DD);
    #pragma unroll
    for (int d4 = 0; d4 < 16; ++d4) {
        float r[4];
        #pragma unroll
        for (int dd = 0; dd < 4; ++dd) {
            int d = d4 * 4 + dd;
            const float4* wr = (const float4*)(Ws + d * DD);
            float a0 = 0.f, a1 = 0.f, a2 = 0.f, a3 = 0.f;
            #pragma unroll
            for (int e4 = 0; e4 < 16; e4 += 4) {
                float4 w0 = wr[e4 + 0], w1 = wr[e4 + 1], w2 = wr[e4 + 2], w3 = wr[e4 + 3];
                a0 += x[e4 + 0].x * w0.x + x[e4 + 0].y * w0.y + x[e4 + 0].z * w0.z + x[e4 + 0].w * w0.w;
                a1 += x[e4 + 1].x * w1.x + x[e4 + 1].y * w1.y + x[e4 + 1].z * w1.z + x[e4 + 1].w * w1.w;
                a2 += x[e4 + 2].x * w2.x + x[e4 + 2].y * w2.y + x[e4 + 2].z * w2.z + x[e4 + 2].w * w2.w;
                a3 += x[e4 + 3].x * w3.x + x[e4 + 3].y * w3.y + x[e4 + 3].z * w3.z + x[e4 + 3].w * w3.w;
            }
            r[dd] = (a0 + a1) + (a2 + a3);
        }
        q[d4] = make_float4(r[0], r[1], r[2], r[3]);
    }
}

// ---------------------------------------------------------------------------
// Baseline-PTX tensor core helpers (no sm_103a-only features)
// ---------------------------------------------------------------------------
__device__ __forceinline__ uint32_t smem_u32(const void* p) {
    uint32_t a;
    asm("{ .reg .u64 t; cvta.to.shared.u64 t, %1; cvt.u32.u64 %0, t; }" : "=r"(a) : "l"(p));
    return a;
}

__device__ __forceinline__ void ldsm4(uint32_t& r0, uint32_t& r1, uint32_t& r2,
                                      uint32_t& r3, uint32_t addr) {
    asm volatile("ldmatrix.sync.aligned.m8n8.x4.shared.b16 {%0,%1,%2,%3}, [%4];"
                 : "=r"(r0), "=r"(r1), "=r"(r2), "=r"(r3) : "r"(addr));
}

__device__ __forceinline__ void mma16816(float* c, const uint32_t* a,
                                         const uint32_t* b) {
    asm volatile(
        "mma.sync.aligned.m16n8k16.row.col.f32.bf16.bf16.f32 "
        "{%0,%1,%2,%3}, {%4,%5,%6,%7}, {%8,%9}, {%0,%1,%2,%3};"
        : "+f"(c[0]), "+f"(c[1]), "+f"(c[2]), "+f"(c[3])
        : "r"(a[0]), "r"(a[1]), "r"(a[2]), "r"(a[3]), "r"(b[0]), "r"(b[1]));
}

// SMEM: 4 tiles of 128 rows x 72 bf16 (pitch 144B; 36 words == 4 mod 32 ->
// ldmatrix row addresses hit distinct bank quartets, conflict-free, no swizzle)
#define PITCHB 144
#define TILEB  (128 * PITCHB)   // 18432
#define SM_AH  0
#define SM_AL  TILEB
#define SM_BH  (2 * TILEB)
#define SM_BL  (3 * TILEB)
#define SM_TOTAL (4 * TILEB)    // 73728 B

// ---------------------------------------------------------------------------
// Stage 2: out[s,i,j] = sum_d x1[s,i,d] * Q[s,j,d] via bf16x3 mma.sync.
// 128x128 tile/CTA, 8 warps (4x2), warp tile 32x64, K=64 resident.
// ---------------------------------------------------------------------------
__global__ __launch_bounds__(256, 2) void gemm_mma(const float* __restrict__ x1,
                                                   const float* __restrict__ bias,
                                                   float* __restrict__ out) {
    extern __shared__ char smem[];
    const uint32_t sb = smem_u32(smem);
    const int tid = threadIdx.x, wid = tid >> 5, lid = tid & 31;
    const int s = blockIdx.z, bi = blockIdx.y, bj = blockIdx.x;
    const int warp_m = wid >> 1;   // 0..3, 32 rows each
    const int warp_n = wid & 1;    // 0..1, 64 cols each

    // ---- Load + split-convert both 128x64 fp32 tiles to bf16 hi/lo ----
    const float4* Ag = (const float4*)(x1 + ((size_t)s * NN + (size_t)bi * 128) * DD);
    const float4* Bg = (const float4*)(g_Q + ((size_t)s * NN + (size_t)bj * 128) * DD);

    #pragma unroll
    for (int half = 0; half < 2; ++half) {
        const float4* G = half ? Bg : Ag;
        char* sh = smem + (half ? SM_BH : SM_AH);
        char* sl = smem + (half ? SM_BL : SM_AL);
        #pragma unroll
        for (int it = 0; it < 4; ++it) {
            int idx = it * 256 + tid;        // 8-float chunk, 0..1023
            int row = idx >> 3;              // 0..127
            int c8  = idx & 7;
            float4 v0 = G[row * 16 + c8 * 2];
            float4 v1 = G[row * 16 + c8 * 2 + 1];
            float f[8] = {v0.x, v0.y, v0.z, v0.w, v1.x, v1.y, v1.z, v1.w};
            uint32_t h[4], l[4];
            #pragma unroll
            for (int p = 0; p < 4; ++p) {
                float a = f[2 * p], b = f[2 * p + 1];
                __nv_bfloat16 ah = __float2bfloat16(a), bh = __float2bfloat16(b);
                float ar = a - __bfloat162float(ah);
                float br = b - __bfloat162float(bh);
                __nv_bfloat162 hp; hp.x = ah; hp.y = bh;
                __nv_bfloat162 lp = __floats2bfloat162_rn(ar, br);
                h[p] = *(uint32_t*)&hp;
                l[p] = *(uint32_t*)&lp;
            }
            uint32_t off = (uint32_t)(row * PITCHB + c8 * 16);
            *(uint4*)(sh + off) = make_uint4(h[0], h[1], h[2], h[3]);
            *(uint4*)(sl + off) = make_uint4(l[0], l[1], l[2], l[3]);
        }
    }
    __syncthreads();

    // ---- Per-lane ldmatrix base addresses ----
    // A fragment (m16k16, row-major): m_off = lid&15, k_off = (lid>>4)*8
    const uint32_t a_lane = (uint32_t)((warp_m * 32 + (lid & 15)) * PITCHB +
                                       ((lid >> 4) * 8) * 2);
    // B fragment (k16n8 col-major == Q row-major): covers two n8 tiles per x4
    // n_off = ((lid>>4)&1)*8 + (lid&7), k_off = ((lid>>3)&1)*8
    const uint32_t b_lane = (uint32_t)((warp_n * 64 + ((lid >> 4) & 1) * 8 + (lid & 7)) * PITCHB +
                                       (((lid >> 3) & 1) * 8) * 2);

    float acc[2][8][4];
    #pragma unroll
    for (int mt = 0; mt < 2; ++mt)
        #pragma unroll
        for (int nt = 0; nt < 8; ++nt)
            #pragma unroll
            for (int r = 0; r < 4; ++r) acc[mt][nt][r] = 0.f;

    // ---- 3 passes: Ah*Bh, Ah*Bl, Al*Bh ----
    #pragma unroll
    for (int pass = 0; pass < 3; ++pass) {
        const uint32_t pa = sb + (pass == 2 ? SM_AL : SM_AH) + a_lane;
        const uint32_t pb = sb + (pass == 1 ? SM_BL : SM_BH) + b_lane;
        #pragma unroll
        for (int ks = 0; ks < 4; ++ks) {
            uint32_t a[2][4];
            #pragma unroll
            for (int mt = 0; mt < 2; ++mt)
                ldsm4(a[mt][0], a[mt][1], a[mt][2], a[mt][3],
                      pa + (uint32_t)(mt * 16 * PITCHB + ks * 32));
            uint32_t b[4][4];
            #pragma unroll
            for (int nq = 0; nq < 4; ++nq)
                ldsm4(b[nq][0], b[nq][1], b[nq][2], b[nq][3],
                      pb + (uint32_t)(nq * 16 * PITCHB + ks * 32));
            #pragma unroll
            for (int mt = 0; mt < 2; ++mt)
                #pragma unroll
                for (int nq = 0; nq < 4; ++nq) {
                    mma16816(acc[mt][2 * nq],     a[mt], &b[nq][0]);
                    mma16816(acc[mt][2 * nq + 1], a[mt], &b[nq][2]);
                }
        }
    }

    // ---- Epilogue: direct register stores, both batch copies ----
    const float bv = *bias;
    const size_t BST = (size_t)SS * NN * NN;
    const size_t i_base = (size_t)bi * 128 + warp_m * 32 + (lid >> 2);
    const size_t j_base = (size_t)bj * 128 + warp_n * 64 + (lid & 3) * 2;

    #pragma unroll
    for (int mt = 0; mt < 2; ++mt) {
        #pragma unroll
        for (int nt = 0; nt < 8; ++nt) {
            float2 v0 = make_float2(acc[mt][nt][0] + bv, acc[mt][nt][1] + bv);
            float2 v1 = make_float2(acc[mt][nt][2] + bv, acc[mt][nt][3] + bv);
            float* d = out + ((size_t)s * NN + i_base + mt * 16) * NN + j_base + nt * 8;
            *(float2*)d = v0;
            *(float2*)(d + 8 * NN) = v1;
            *(float2*)(d + BST) = v0;
            *(float2*)(d + BST + 8 * NN) = v1;
        }
    }
}

// ---------------------------------------------------------------------------
// Launch
// ---------------------------------------------------------------------------
extern "C" void kernel_launch(void* const* d_in, const int* in_sizes, int n_in,
                              void* d_out, int out_size) {
    const float* x0   = (const float*)d_in[0];  // tensor0 (S,N,D)
    const float* x1   = (const float*)d_in[1];  // tensor1 (S,N,D)
    const float* W    = (const float*)d_in[2];  // kernel (D,D)
    const float* bias = (const float*)d_in[3];  // scalar
    float* out = (float*)d_out;                 // (2,S,N,N)

    q_kernel<<<(SS * NN) / 256, 256>>>(x0, W);

    cudaFuncSetAttribute(gemm_mma, cudaFuncAttributeMaxDynamicSharedMemorySize, SM_TOTAL);
    dim3 grid(NN / 128, NN / 128, SS);
    gemm_mma<<<grid, 256, SM_TOTAL>>>(x1, bias, out);
}